// round 1
// baseline (speedup 1.0000x reference)
#include <cuda_runtime.h>

#define LOG2E 1.44269504088896f

// Scratch: q,k,v in [B*H, S, 64] layout; attn out in [B, S, 1024] layout.
__device__ float g_q[8388608];
__device__ float g_k[8388608];
__device__ float g_v[8388608];
__device__ float g_attn[8388608];

// ---------------------------------------------------------------------------
// Fused QKV projection (+RoPE for Q,K).  C = X @ W^T, W in {Wq,Wk,Wv}.
// BM=128, BN=64, BK=32, 256 threads, 8x4 per thread.
// Smem stored k-major (transposed) so inner loop is 3x LDS.128 + 32 FFMA.
// ---------------------------------------------------------------------------
__global__ __launch_bounds__(256) void qkv_proj_kernel(
    const float* __restrict__ X,
    const float* __restrict__ Wq, const float* __restrict__ Wk,
    const float* __restrict__ Wv,
    const float* __restrict__ cos_f, const float* __restrict__ sin_f)
{
    __shared__ float As[32 * 132];   // [k][m], pitch 132 (16B-aligned float4 reads)
    __shared__ float Bs[32 * 68];    // [k][n], pitch 68

    const int tid = threadIdx.x;
    const int tx = tid & 15, ty = tid >> 4;
    const int bx = blockIdx.x;              // 0..47
    const int wsel = bx >> 4;               // 0=q, 1=k, 2=v
    const int nt = bx & 15;                 // col tile within matrix (== head)
    const int m0 = blockIdx.y * 128;
    const int n0 = nt * 64;
    const float* __restrict__ W = (wsel == 0) ? Wq : (wsel == 1 ? Wk : Wv);

    float acc[8][4];
    #pragma unroll
    for (int i = 0; i < 8; i++)
        #pragma unroll
        for (int j = 0; j < 4; j++) acc[i][j] = 0.f;

    for (int k0 = 0; k0 < 1024; k0 += 32) {
        #pragma unroll
        for (int i = 0; i < 4; i++) {           // A: 128x32 = 1024 float4
            int idx = tid + i * 256;
            int row = idx >> 3, c4 = idx & 7;
            float4 v = *(const float4*)(X + (size_t)(m0 + row) * 1024 + k0 + c4 * 4);
            int o = (c4 * 4) * 132 + row;
            As[o] = v.x; As[o + 132] = v.y; As[o + 264] = v.z; As[o + 396] = v.w;
        }
        #pragma unroll
        for (int i = 0; i < 2; i++) {           // B: 64x32 = 512 float4
            int idx = tid + i * 256;
            int row = idx >> 3, c4 = idx & 7;
            float4 v = *(const float4*)(W + (size_t)(n0 + row) * 1024 + k0 + c4 * 4);
            int o = (c4 * 4) * 68 + row;
            Bs[o] = v.x; Bs[o + 68] = v.y; Bs[o + 136] = v.z; Bs[o + 204] = v.w;
        }
        __syncthreads();
        #pragma unroll 16
        for (int k = 0; k < 32; k++) {
            float4 b4 = *(const float4*)&Bs[k * 68 + tx * 4];
            float4 a0 = *(const float4*)&As[k * 132 + ty * 8];
            float4 a1 = *(const float4*)&As[k * 132 + ty * 8 + 4];
            float a[8] = {a0.x, a0.y, a0.z, a0.w, a1.x, a1.y, a1.z, a1.w};
            float b[4] = {b4.x, b4.y, b4.z, b4.w};
            #pragma unroll
            for (int ii = 0; ii < 8; ii++)
                #pragma unroll
                for (int jj = 0; jj < 4; jj++)
                    acc[ii][jj] = fmaf(a[ii], b[jj], acc[ii][jj]);
        }
        __syncthreads();
    }

    float* dst = (wsel == 0) ? g_q : (wsel == 1 ? g_k : g_v);
    const int b = m0 >> 11;     // batch (block never straddles: 2048 % 128 == 0)
    const int h = nt;           // 64-wide col tile == one head
    #pragma unroll
    for (int ii = 0; ii < 8; ii++) {
        int m = m0 + ty * 8 + ii;
        int s = m & 2047;
        float4 r;
        if (wsel < 2) {
            // RoPE: cols tx*4..tx*4+3 -> pairs (2i,2i+1) with i = tx*2, tx*2+1
            float c0 = cos_f[s * 32 + tx * 2],     s0 = sin_f[s * 32 + tx * 2];
            float c1 = cos_f[s * 32 + tx * 2 + 1], s1 = sin_f[s * 32 + tx * 2 + 1];
            r.x = acc[ii][0] * c0 - acc[ii][1] * s0;
            r.y = acc[ii][0] * s0 + acc[ii][1] * c0;
            r.z = acc[ii][2] * c1 - acc[ii][3] * s1;
            r.w = acc[ii][2] * s1 + acc[ii][3] * c1;
        } else {
            r = make_float4(acc[ii][0], acc[ii][1], acc[ii][2], acc[ii][3]);
        }
        *(float4*)(dst + ((size_t)(b * 16 + h) * 2048 + s) * 64 + tx * 4) = r;
    }
}

// ---------------------------------------------------------------------------
// Flash attention: 64 q rows x 64 kv per tile, 256 threads, 4x4 per thread
// (strided-free: rows ty*4+ii, cols tx*4+jj).  Online softmax, causal.
// Smem: Qs/Ks d-major [d][row] so score loop is 2x LDS.128 + 16 FFMA per d.
// P reuses the K buffer as [kv][q] so the PV loop is also vector-fed.
// ---------------------------------------------------------------------------
__global__ __launch_bounds__(256) void attn_kernel()
{
    extern __shared__ float sm[];
    float* Qs = sm;               // [64][68]  Qs[d*68 + q]
    float* Ks = sm + 4352;        // [64][68]  Ks[d*68 + kv]; reused as Ps[kv*68 + q]
    float* Vs = sm + 8704;        // [64][68]  Vs[kv*68 + d]

    const int tid = threadIdx.x, tx = tid & 15, ty = tid >> 4;
    const int qt = blockIdx.x, bh = blockIdx.y;
    const int q0 = qt * 64;
    const float* __restrict__ Qg = g_q + (size_t)bh * 2048 * 64;
    const float* __restrict__ Kg = g_k + (size_t)bh * 2048 * 64;
    const float* __restrict__ Vg = g_v + (size_t)bh * 2048 * 64;

    // load Q tile transposed (once)
    #pragma unroll
    for (int i = 0; i < 4; i++) {
        int idx = tid + i * 256;
        int row = idx >> 4, c4 = idx & 15;
        float4 v = *(const float4*)(Qg + (q0 + row) * 64 + c4 * 4);
        int o = (c4 * 4) * 68 + row;
        Qs[o] = v.x; Qs[o + 68] = v.y; Qs[o + 136] = v.z; Qs[o + 204] = v.w;
    }

    float m_i[4], l_i[4], o_acc[4][4];
    #pragma unroll
    for (int i = 0; i < 4; i++) {
        m_i[i] = -1e30f; l_i[i] = 0.f;
        #pragma unroll
        for (int j = 0; j < 4; j++) o_acc[i][j] = 0.f;
    }

    for (int t = 0; t <= qt; t++) {
        const int kv0 = t * 64;
        __syncthreads();   // protects Ps/Vs of previous iter (and Q stores on iter 0)
        #pragma unroll
        for (int i = 0; i < 4; i++) {
            int idx = tid + i * 256;
            int row = idx >> 4, c4 = idx & 15;
            float4 kv = *(const float4*)(Kg + (kv0 + row) * 64 + c4 * 4);
            int o = (c4 * 4) * 68 + row;
            Ks[o] = kv.x; Ks[o + 68] = kv.y; Ks[o + 136] = kv.z; Ks[o + 204] = kv.w;
            float4 vv = *(const float4*)(Vg + (kv0 + row) * 64 + c4 * 4);
            *(float4*)&Vs[row * 68 + c4 * 4] = vv;
        }
        __syncthreads();

        // S = Q @ K^T
        float sacc[4][4];
        #pragma unroll
        for (int i = 0; i < 4; i++)
            #pragma unroll
            for (int j = 0; j < 4; j++) sacc[i][j] = 0.f;
        #pragma unroll 16
        for (int d = 0; d < 64; d++) {
            float4 q4 = *(const float4*)&Qs[d * 68 + ty * 4];
            float4 k4 = *(const float4*)&Ks[d * 68 + tx * 4];
            float qa[4] = {q4.x, q4.y, q4.z, q4.w};
            float ka[4] = {k4.x, k4.y, k4.z, k4.w};
            #pragma unroll
            for (int ii = 0; ii < 4; ii++)
                #pragma unroll
                for (int jj = 0; jj < 4; jj++)
                    sacc[ii][jj] = fmaf(qa[ii], ka[jj], sacc[ii][jj]);
        }

        // scale + causal mask + online softmax
        #pragma unroll
        for (int ii = 0; ii < 4; ii++) {
            const int qi = q0 + ty * 4 + ii;
            float rm = -1e30f;
            #pragma unroll
            for (int jj = 0; jj < 4; jj++) {
                float v = sacc[ii][jj] * 0.125f;
                if (kv0 + tx * 4 + jj > qi) v = -1e9f;
                sacc[ii][jj] = v;
                rm = fmaxf(rm, v);
            }
            rm = fmaxf(rm, __shfl_xor_sync(0xffffffffu, rm, 1));
            rm = fmaxf(rm, __shfl_xor_sync(0xffffffffu, rm, 2));
            rm = fmaxf(rm, __shfl_xor_sync(0xffffffffu, rm, 4));
            rm = fmaxf(rm, __shfl_xor_sync(0xffffffffu, rm, 8));
            float mn = fmaxf(m_i[ii], rm);
            float al = exp2f((m_i[ii] - mn) * LOG2E);
            m_i[ii] = mn;
            float ps = 0.f;
            #pragma unroll
            for (int jj = 0; jj < 4; jj++) {
                float p = exp2f((sacc[ii][jj] - mn) * LOG2E);
                sacc[ii][jj] = p;
                ps += p;
            }
            ps += __shfl_xor_sync(0xffffffffu, ps, 1);
            ps += __shfl_xor_sync(0xffffffffu, ps, 2);
            ps += __shfl_xor_sync(0xffffffffu, ps, 4);
            ps += __shfl_xor_sync(0xffffffffu, ps, 8);
            l_i[ii] = l_i[ii] * al + ps;
            #pragma unroll
            for (int jj = 0; jj < 4; jj++) o_acc[ii][jj] *= al;
        }

        __syncthreads();   // everyone done reading Ks before it becomes Ps
        #pragma unroll
        for (int jj = 0; jj < 4; jj++) {
            float4 p = make_float4(sacc[0][jj], sacc[1][jj], sacc[2][jj], sacc[3][jj]);
            *(float4*)&Ks[(tx * 4 + jj) * 68 + ty * 4] = p;   // Ps[kv][q]
        }
        __syncthreads();

        // O += P @ V
        #pragma unroll 16
        for (int kv = 0; kv < 64; kv++) {
            float4 p4 = *(const float4*)&Ks[kv * 68 + ty * 4];
            float4 v4 = *(const float4*)&Vs[kv * 68 + tx * 4];
            float pa[4] = {p4.x, p4.y, p4.z, p4.w};
            float va[4] = {v4.x, v4.y, v4.z, v4.w};
            #pragma unroll
            for (int ii = 0; ii < 4; ii++)
                #pragma unroll
                for (int jj = 0; jj < 4; jj++)
                    o_acc[ii][jj] = fmaf(pa[ii], va[jj], o_acc[ii][jj]);
        }
    }

    // write O in [B, S, H, D] (= row-major [8192, 1024]) for the O projection
    const int b = bh >> 4, h = bh & 15;
    #pragma unroll
    for (int ii = 0; ii < 4; ii++) {
        float inv = 1.0f / l_i[ii];
        int s = q0 + ty * 4 + ii;
        float4 o = make_float4(o_acc[ii][0] * inv, o_acc[ii][1] * inv,
                               o_acc[ii][2] * inv, o_acc[ii][3] * inv);
        *(float4*)(g_attn + (size_t)(b * 2048 + s) * 1024 + h * 64 + tx * 4) = o;
    }
}

// ---------------------------------------------------------------------------
// Output projection: out = g_attn @ Wo^T (plain GEMM, same tiling).
// ---------------------------------------------------------------------------
__global__ __launch_bounds__(256) void oproj_kernel(
    const float* __restrict__ Wo, float* __restrict__ out)
{
    __shared__ float As[32 * 132];
    __shared__ float Bs[32 * 68];

    const int tid = threadIdx.x;
    const int tx = tid & 15, ty = tid >> 4;
    const int m0 = blockIdx.y * 128;
    const int n0 = blockIdx.x * 64;
    const float* __restrict__ A = g_attn;

    float acc[8][4];
    #pragma unroll
    for (int i = 0; i < 8; i++)
        #pragma unroll
        for (int j = 0; j < 4; j++) acc[i][j] = 0.f;

    for (int k0 = 0; k0 < 1024; k0 += 32) {
        #pragma unroll
        for (int i = 0; i < 4; i++) {
            int idx = tid + i * 256;
            int row = idx >> 3, c4 = idx & 7;
            float4 v = *(const float4*)(A + (size_t)(m0 + row) * 1024 + k0 + c4 * 4);
            int o = (c4 * 4) * 132 + row;
            As[o] = v.x; As[o + 132] = v.y; As[o + 264] = v.z; As[o + 396] = v.w;
        }
        #pragma unroll
        for (int i = 0; i < 2; i++) {
            int idx = tid + i * 256;
            int row = idx >> 3, c4 = idx & 7;
            float4 v = *(const float4*)(Wo + (size_t)(n0 + row) * 1024 + k0 + c4 * 4);
            int o = (c4 * 4) * 68 + row;
            Bs[o] = v.x; Bs[o + 68] = v.y; Bs[o + 136] = v.z; Bs[o + 204] = v.w;
        }
        __syncthreads();
        #pragma unroll 16
        for (int k = 0; k < 32; k++) {
            float4 b4 = *(const float4*)&Bs[k * 68 + tx * 4];
            float4 a0 = *(const float4*)&As[k * 132 + ty * 8];
            float4 a1 = *(const float4*)&As[k * 132 + ty * 8 + 4];
            float a[8] = {a0.x, a0.y, a0.z, a0.w, a1.x, a1.y, a1.z, a1.w};
            float b[4] = {b4.x, b4.y, b4.z, b4.w};
            #pragma unroll
            for (int ii = 0; ii < 8; ii++)
                #pragma unroll
                for (int jj = 0; jj < 4; jj++)
                    acc[ii][jj] = fmaf(a[ii], b[jj], acc[ii][jj]);
        }
        __syncthreads();
    }

    #pragma unroll
    for (int ii = 0; ii < 8; ii++) {
        int m = m0 + ty * 8 + ii;
        float4 r = make_float4(acc[ii][0], acc[ii][1], acc[ii][2], acc[ii][3]);
        *(float4*)(out + (size_t)m * 1024 + n0 + tx * 4) = r;
    }
}

// ---------------------------------------------------------------------------
extern "C" void kernel_launch(void* const* d_in, const int* in_sizes, int n_in,
                              void* d_out, int out_size) {
    const float* x     = (const float*)d_in[0];
    const float* cos_f = (const float*)d_in[1];
    const float* sin_f = (const float*)d_in[2];
    // d_in[3] = causal_mask: unused (mask synthesized analytically)
    const float* wq    = (const float*)d_in[4];
    const float* wk    = (const float*)d_in[5];
    const float* wv    = (const float*)d_in[6];
    const float* wo    = (const float*)d_in[7];
    float* out = (float*)d_out;

    qkv_proj_kernel<<<dim3(48, 64), 256>>>(x, wq, wk, wv, cos_f, sin_f);

    cudaFuncSetAttribute(attn_kernel,
                         cudaFuncAttributeMaxDynamicSharedMemorySize, 52224);
    attn_kernel<<<dim3(32, 64), 256, 52224>>>();

    oproj_kernel<<<dim3(16, 64), 256>>>(wo, out);
}